// round 4
// baseline (speedup 1.0000x reference)
#include <cuda_runtime.h>

#define B_N 32768
#define D_N 1024
#define S_N 64
#define O_N 4
#define SPW 8   // samples per warp in gemm

__device__ int g_counts[S_N];
__device__ int g_cursor[S_N];
__device__ int g_perm[B_N];

// ---------------------------------------------------------------- init
__global__ void k_init() {
    if (threadIdx.x < S_N) g_counts[threadIdx.x] = 0;
}

// ---------------------------------------------------------------- histogram (block-aggregated)
__global__ void k_hist(const int* __restrict__ sid) {
    __shared__ int h[S_N];
    int t = threadIdx.x;
    if (t < S_N) h[t] = 0;
    __syncthreads();
    int i = blockIdx.x * blockDim.x + t;
    atomicAdd(&h[sid[i]], 1);
    __syncthreads();
    if (t < S_N && h[t] > 0) atomicAdd(&g_counts[t], h[t]);
}

// ---------------------------------------------------------------- exclusive scan (64 elems)
__global__ void k_scan() {
    if (threadIdx.x == 0) {
        int acc = 0;
        for (int s = 0; s < S_N; ++s) {
            g_cursor[s] = acc;
            acc += g_counts[s];
        }
    }
}

// ---------------------------------------------------------------- scatter (block-aggregated reservation)
__global__ void k_scatter(const int* __restrict__ sid) {
    __shared__ int h[S_N];
    __shared__ int base[S_N];
    int t = threadIdx.x;
    if (t < S_N) h[t] = 0;
    __syncthreads();
    int i = blockIdx.x * blockDim.x + t;
    int s = sid[i];
    int r = atomicAdd(&h[s], 1);
    __syncthreads();
    if (t < S_N) base[t] = (h[t] > 0) ? atomicAdd(&g_cursor[t], h[t]) : 0;
    __syncthreads();
    g_perm[base[s] + r] = i;
}

// ---------------------------------------------------------------- gemm: warp handles SPW sorted samples
__global__ void __launch_bounds__(256) k_gemm(
    const float* __restrict__ x,
    const int*   __restrict__ sid,
    const float* __restrict__ W,
    const float* __restrict__ bias,
    float*       __restrict__ out)
{
    int warp = (blockIdx.x * blockDim.x + threadIdx.x) >> 5;
    int lane = threadIdx.x & 31;
    int base = warp * SPW;

    int idx[SPW], sd[SPW];
#pragma unroll
    for (int s = 0; s < SPW; ++s) {
        idx[s] = g_perm[base + s];
        sd[s]  = sid[idx[s]];
    }

    bool uni = true;
#pragma unroll
    for (int s = 1; s < SPW; ++s) uni &= (sd[s] == sd[0]);

    float acc[SPW][O_N];
#pragma unroll
    for (int s = 0; s < SPW; ++s)
#pragma unroll
        for (int o = 0; o < O_N; ++o) acc[s][o] = 0.0f;

    if (uni) {
        // fast path: one W row load serves all SPW samples
        const float4* Wp = reinterpret_cast<const float4*>(W) + sd[0] * D_N;
#pragma unroll 4
        for (int d = lane; d < D_N; d += 32) {
            float4 w = Wp[d];
#pragma unroll
            for (int s = 0; s < SPW; ++s) {
                float xv = x[idx[s] * D_N + d];
                acc[s][0] += xv * w.x;
                acc[s][1] += xv * w.y;
                acc[s][2] += xv * w.z;
                acc[s][3] += xv * w.w;
            }
        }
    } else {
        // boundary warp: per-sample W
#pragma unroll
        for (int s = 0; s < SPW; ++s) {
            const float4* Wp = reinterpret_cast<const float4*>(W) + sd[s] * D_N;
            const float*  xp = x + idx[s] * D_N;
#pragma unroll 4
            for (int d = lane; d < D_N; d += 32) {
                float4 w  = Wp[d];
                float  xv = xp[d];
                acc[s][0] += xv * w.x;
                acc[s][1] += xv * w.y;
                acc[s][2] += xv * w.z;
                acc[s][3] += xv * w.w;
            }
        }
    }

    // warp reduction (butterfly -> all lanes hold totals)
#pragma unroll
    for (int s = 0; s < SPW; ++s)
#pragma unroll
        for (int o = 0; o < O_N; ++o) {
#pragma unroll
            for (int off = 16; off; off >>= 1)
                acc[s][o] += __shfl_xor_sync(0xffffffffu, acc[s][o], off);
        }

    // lane s writes sample s (float4 store, 16B aligned)
#pragma unroll
    for (int s = 0; s < SPW; ++s) {
        if (lane == s) {
            float4 bb = reinterpret_cast<const float4*>(bias)[sd[s]];
            float4 r;
            r.x = acc[s][0] + bb.x;
            r.y = acc[s][1] + bb.y;
            r.z = acc[s][2] + bb.z;
            r.w = acc[s][3] + bb.w;
            reinterpret_cast<float4*>(out)[idx[s]] = r;
        }
    }
}

// ---------------------------------------------------------------- launch
extern "C" void kernel_launch(void* const* d_in, const int* in_sizes, int n_in,
                              void* d_out, int out_size) {
    const float* x    = (const float*)d_in[0];   // [B, D]
    const int*   sid  = (const int*)d_in[1];     // [B]
    const float* W    = (const float*)d_in[2];   // [S, D, O]
    const float* bias = (const float*)d_in[3];   // [S, O]
    float*       out  = (float*)d_out;           // [B, O]

    (void)in_sizes; (void)n_in; (void)out_size;

    k_init<<<1, 64>>>();
    k_hist<<<B_N / 256, 256>>>(sid);
    k_scan<<<1, 32>>>();
    k_scatter<<<B_N / 256, 256>>>(sid);
    k_gemm<<<B_N / (SPW * 8), 256>>>(x, sid, W, bias, out);
}

// round 5
// speedup vs baseline: 1.4040x; 1.4040x over previous
#include <cuda_runtime.h>

#define B_N 32768
#define D_N 1024
#define S_N 64
#define O_N 4
#define SPW 8            // samples per warp in gemm
#define NBLK 128         // hist/scatter blocks (256 threads each)

__device__ int g_bh[NBLK][S_N];    // per-block histogram
__device__ int g_base[NBLK][S_N];  // per-block scatter base
__device__ int g_perm[B_N];

// ---------------------------------------------------------------- histogram (no init needed: pure overwrite)
__global__ void k_hist(const int* __restrict__ sid) {
    __shared__ int h[S_N];
    int t = threadIdx.x;
    if (t < S_N) h[t] = 0;
    __syncthreads();
    int i = blockIdx.x * blockDim.x + t;
    atomicAdd(&h[sid[i]], 1);
    __syncthreads();
    if (t < S_N) g_bh[blockIdx.x][t] = h[t];
}

// ---------------------------------------------------------------- scan: subject offsets + per-block bases
__global__ void k_scan() {
    __shared__ int cnt[S_N];
    __shared__ int off[S_N];
    int s = threadIdx.x;           // 64 threads
    int c = 0;
#pragma unroll 8
    for (int b = 0; b < NBLK; ++b) c += g_bh[b][s];
    cnt[s] = c;
    __syncthreads();
    if (s == 0) {
        int a = 0;
        for (int j = 0; j < S_N; ++j) { off[j] = a; a += cnt[j]; }
    }
    __syncthreads();
    int run = off[s];
    for (int b = 0; b < NBLK; ++b) {
        g_base[b][s] = run;
        run += g_bh[b][s];
    }
}

// ---------------------------------------------------------------- scatter (shared-atomic rank, precomputed base)
__global__ void k_scatter(const int* __restrict__ sid) {
    __shared__ int h[S_N];
    int t = threadIdx.x;
    if (t < S_N) h[t] = 0;
    __syncthreads();
    int i = blockIdx.x * blockDim.x + t;
    int s = sid[i];
    int r = atomicAdd(&h[s], 1);
    g_perm[g_base[blockIdx.x][s] + r] = i;
}

// ---------------------------------------------------------------- gemm: warp handles SPW sorted samples, float4 loads
__global__ void __launch_bounds__(256, 2) k_gemm(
    const float* __restrict__ x,
    const int*   __restrict__ sid,
    const float* __restrict__ W,
    const float* __restrict__ bias,
    float*       __restrict__ out)
{
    int warp = (blockIdx.x * blockDim.x + threadIdx.x) >> 5;
    int lane = threadIdx.x & 31;
    int base = warp * SPW;

    int idx[SPW], sd[SPW];
#pragma unroll
    for (int s = 0; s < SPW; ++s) {
        idx[s] = g_perm[base + s];
        sd[s]  = sid[idx[s]];
    }

    bool uni = true;
#pragma unroll
    for (int s = 1; s < SPW; ++s) uni &= (sd[s] == sd[0]);

    float acc[SPW][O_N];
#pragma unroll
    for (int s = 0; s < SPW; ++s)
#pragma unroll
        for (int o = 0; o < O_N; ++o) acc[s][o] = 0.0f;

    const float4* x4 = reinterpret_cast<const float4*>(x);

    if (uni) {
        // fast path: one subject's W rows serve all SPW samples
        const float4* W4 = reinterpret_cast<const float4*>(W) + sd[0] * D_N;
#pragma unroll 2
        for (int k = 0; k < 8; ++k) {
            int dv = k * 32 + lane;            // float4 index within x row (0..255)
            // 8 independent 16B x loads -> 32 lines in flight per warp
            float4 xv[SPW];
#pragma unroll
            for (int s = 0; s < SPW; ++s)
                xv[s] = x4[idx[s] * (D_N / 4) + dv];
            // 4 consecutive W rows (each = float4 of O outputs), L1-resident tile
            float4 w0 = W4[4 * dv + 0];
            float4 w1 = W4[4 * dv + 1];
            float4 w2 = W4[4 * dv + 2];
            float4 w3 = W4[4 * dv + 3];
#pragma unroll
            for (int s = 0; s < SPW; ++s) {
                acc[s][0] += xv[s].x * w0.x + xv[s].y * w1.x + xv[s].z * w2.x + xv[s].w * w3.x;
                acc[s][1] += xv[s].x * w0.y + xv[s].y * w1.y + xv[s].z * w2.y + xv[s].w * w3.y;
                acc[s][2] += xv[s].x * w0.z + xv[s].y * w1.z + xv[s].z * w2.z + xv[s].w * w3.z;
                acc[s][3] += xv[s].x * w0.w + xv[s].y * w1.w + xv[s].z * w2.w + xv[s].w * w3.w;
            }
        }
    } else {
        // boundary warp (subject change within the 8): per-sample W
#pragma unroll
        for (int s = 0; s < SPW; ++s) {
            const float4* W4 = reinterpret_cast<const float4*>(W) + sd[s] * D_N;
            const float4* xp = x4 + idx[s] * (D_N / 4);
            for (int k = 0; k < 8; ++k) {
                int dv = k * 32 + lane;
                float4 xv = xp[dv];
                float4 w0 = W4[4 * dv + 0];
                float4 w1 = W4[4 * dv + 1];
                float4 w2 = W4[4 * dv + 2];
                float4 w3 = W4[4 * dv + 3];
                acc[s][0] += xv.x * w0.x + xv.y * w1.x + xv.z * w2.x + xv.w * w3.x;
                acc[s][1] += xv.x * w0.y + xv.y * w1.y + xv.z * w2.y + xv.w * w3.y;
                acc[s][2] += xv.x * w0.z + xv.y * w1.z + xv.z * w2.z + xv.w * w3.z;
                acc[s][3] += xv.x * w0.w + xv.y * w1.w + xv.z * w2.w + xv.w * w3.w;
            }
        }
    }

    // warp butterfly reduction
#pragma unroll
    for (int s = 0; s < SPW; ++s)
#pragma unroll
        for (int o = 0; o < O_N; ++o) {
#pragma unroll
            for (int off = 16; off; off >>= 1)
                acc[s][o] += __shfl_xor_sync(0xffffffffu, acc[s][o], off);
        }

    // lane s writes sample s (float4 store)
#pragma unroll
    for (int s = 0; s < SPW; ++s) {
        if (lane == s) {
            float4 bb = reinterpret_cast<const float4*>(bias)[sd[s]];
            float4 r;
            r.x = acc[s][0] + bb.x;
            r.y = acc[s][1] + bb.y;
            r.z = acc[s][2] + bb.z;
            r.w = acc[s][3] + bb.w;
            reinterpret_cast<float4*>(out)[idx[s]] = r;
        }
    }
}

// ---------------------------------------------------------------- launch
extern "C" void kernel_launch(void* const* d_in, const int* in_sizes, int n_in,
                              void* d_out, int out_size) {
    const float* x    = (const float*)d_in[0];   // [B, D]
    const int*   sid  = (const int*)d_in[1];     // [B]
    const float* W    = (const float*)d_in[2];   // [S, D, O]
    const float* bias = (const float*)d_in[3];   // [S, O]
    float*       out  = (float*)d_out;           // [B, O]

    (void)in_sizes; (void)n_in; (void)out_size;

    k_hist<<<NBLK, 256>>>(sid);
    k_scan<<<1, 64>>>();
    k_scatter<<<NBLK, 256>>>(sid);
    k_gemm<<<B_N / (SPW * 8), 256>>>(x, sid, W, bias, out);
}

// round 6
// speedup vs baseline: 1.4713x; 1.0479x over previous
#include <cuda_runtime.h>

#define B_N 32768
#define D_N 1024
#define S_N 64
#define O_N 4
#define SPW 4            // samples per warp in gemm
#define NBLK 128         // hist/scatter blocks (256 threads each)
#define TBLK 64          // transpose blocks appended to hist grid

__device__ int   g_bh[NBLK][S_N];    // per-block histogram
__device__ int   g_base[NBLK][S_N];  // per-block scatter base
__device__ int   g_perm[B_N];
__device__ float g_Wt[S_N * O_N * D_N];   // W transposed to [S][O][D] (1 MB scratch)

// ---------------------------------------------------------------- hist + W transpose (fused, disjoint blocks)
__global__ void k_pre(const int* __restrict__ sid, const float4* __restrict__ W4) {
    if (blockIdx.x < NBLK) {
        // histogram part
        __shared__ int h[S_N];
        int t = threadIdx.x;
        if (t < S_N) h[t] = 0;
        __syncthreads();
        int i = blockIdx.x * 256 + t;
        atomicAdd(&h[sid[i]], 1);
        __syncthreads();
        if (t < S_N) g_bh[blockIdx.x][t] = h[t];
    } else {
        // transpose part: W[s][d][o] (float4 per d) -> Wt[s][o][d]
        int b = blockIdx.x - NBLK;               // 0..TBLK-1
#pragma unroll
        for (int j = 0; j < 4; ++j) {
            int t = b * 1024 + j * 256 + threadIdx.x;   // 0..65535 = S*D
            int s = t >> 10;
            int d = t & 1023;
            float4 w = W4[t];
            g_Wt[(s * 4 + 0) * D_N + d] = w.x;
            g_Wt[(s * 4 + 1) * D_N + d] = w.y;
            g_Wt[(s * 4 + 2) * D_N + d] = w.z;
            g_Wt[(s * 4 + 3) * D_N + d] = w.w;
        }
    }
}

// ---------------------------------------------------------------- scan: subject offsets + per-block bases
__global__ void k_scan() {
    __shared__ int cnt[S_N];
    __shared__ int off[S_N];
    int s = threadIdx.x;           // 64 threads
    int c = 0;
#pragma unroll 8
    for (int b = 0; b < NBLK; ++b) c += g_bh[b][s];
    cnt[s] = c;
    __syncthreads();
    if (s == 0) {
        int a = 0;
        for (int j = 0; j < S_N; ++j) { off[j] = a; a += cnt[j]; }
    }
    __syncthreads();
    int run = off[s];
    for (int b = 0; b < NBLK; ++b) {
        g_base[b][s] = run;
        run += g_bh[b][s];
    }
}

// ---------------------------------------------------------------- scatter (shared-atomic rank, precomputed base)
__global__ void k_scatter(const int* __restrict__ sid) {
    __shared__ int h[S_N];
    int t = threadIdx.x;
    if (t < S_N) h[t] = 0;
    __syncthreads();
    int i = blockIdx.x * blockDim.x + t;
    int s = sid[i];
    int r = atomicAdd(&h[s], 1);
    g_perm[g_base[blockIdx.x][s] + r] = i;
}

// ---------------------------------------------------------------- gemm: warp handles SPW sorted samples
__global__ void __launch_bounds__(256, 3) k_gemm(
    const float* __restrict__ x,
    const int*   __restrict__ sid,
    const float* __restrict__ bias,
    float*       __restrict__ out)
{
    int warp = (blockIdx.x * blockDim.x + threadIdx.x) >> 5;
    int lane = threadIdx.x & 31;
    int base = warp * SPW;

    int idx[SPW], sd[SPW];
#pragma unroll
    for (int s = 0; s < SPW; ++s) {
        idx[s] = g_perm[base + s];
        sd[s]  = sid[idx[s]];
    }

    bool uni = true;
#pragma unroll
    for (int s = 1; s < SPW; ++s) uni &= (sd[s] == sd[0]);

    float acc[SPW][O_N];
#pragma unroll
    for (int s = 0; s < SPW; ++s)
#pragma unroll
        for (int o = 0; o < O_N; ++o) acc[s][o] = 0.0f;

    const float4* x4 = reinterpret_cast<const float4*>(x);

    if (uni) {
        // fast path: one subject's transposed W serves all SPW samples.
        // Wt rows are [O][D]: lane-contiguous float4 loads -> 4 wavefronts each.
        const float4* Wt4 = reinterpret_cast<const float4*>(g_Wt) + sd[0] * (O_N * D_N / 4);
#pragma unroll
        for (int k = 0; k < 8; ++k) {
            int dv = k * 32 + lane;                 // float4 index within D (0..255)
            float4 xv[SPW];
#pragma unroll
            for (int s = 0; s < SPW; ++s)
                xv[s] = x4[idx[s] * (D_N / 4) + dv];
            float4 w0 = Wt4[0 * 256 + dv];
            float4 w1 = Wt4[1 * 256 + dv];
            float4 w2 = Wt4[2 * 256 + dv];
            float4 w3 = Wt4[3 * 256 + dv];
#pragma unroll
            for (int s = 0; s < SPW; ++s) {
                acc[s][0] += xv[s].x * w0.x + xv[s].y * w0.y + xv[s].z * w0.z + xv[s].w * w0.w;
                acc[s][1] += xv[s].x * w1.x + xv[s].y * w1.y + xv[s].z * w1.z + xv[s].w * w1.w;
                acc[s][2] += xv[s].x * w2.x + xv[s].y * w2.y + xv[s].z * w2.z + xv[s].w * w2.w;
                acc[s][3] += xv[s].x * w3.x + xv[s].y * w3.y + xv[s].z * w3.z + xv[s].w * w3.w;
            }
        }
    } else {
        // boundary warp (subject change within the SPW): per-sample W
#pragma unroll
        for (int s = 0; s < SPW; ++s) {
            const float4* Wt4 = reinterpret_cast<const float4*>(g_Wt) + sd[s] * (O_N * D_N / 4);
            const float4* xp  = x4 + idx[s] * (D_N / 4);
            for (int k = 0; k < 8; ++k) {
                int dv = k * 32 + lane;
                float4 xv = xp[dv];
                float4 w0 = Wt4[0 * 256 + dv];
                float4 w1 = Wt4[1 * 256 + dv];
                float4 w2 = Wt4[2 * 256 + dv];
                float4 w3 = Wt4[3 * 256 + dv];
                acc[s][0] += xv.x * w0.x + xv.y * w0.y + xv.z * w0.z + xv.w * w0.w;
                acc[s][1] += xv.x * w1.x + xv.y * w1.y + xv.z * w1.z + xv.w * w1.w;
                acc[s][2] += xv.x * w2.x + xv.y * w2.y + xv.z * w2.z + xv.w * w2.w;
                acc[s][3] += xv.x * w3.x + xv.y * w3.y + xv.z * w3.z + xv.w * w3.w;
            }
        }
    }

    // warp butterfly reduction (all lanes end with totals)
#pragma unroll
    for (int s = 0; s < SPW; ++s)
#pragma unroll
        for (int o = 0; o < O_N; ++o) {
#pragma unroll
            for (int off = 16; off; off >>= 1)
                acc[s][o] += __shfl_xor_sync(0xffffffffu, acc[s][o], off);
        }

    // lane s writes sample s (float4 store)
    if (lane < SPW) {
        int s = lane;
        float4 bb = reinterpret_cast<const float4*>(bias)[sd[s]];
        float4 r;
        r.x = acc[s][0] + bb.x;
        r.y = acc[s][1] + bb.y;
        r.z = acc[s][2] + bb.z;
        r.w = acc[s][3] + bb.w;
        reinterpret_cast<float4*>(out)[idx[s]] = r;
    }
}

// ---------------------------------------------------------------- launch
extern "C" void kernel_launch(void* const* d_in, const int* in_sizes, int n_in,
                              void* d_out, int out_size) {
    const float* x    = (const float*)d_in[0];   // [B, D]
    const int*   sid  = (const int*)d_in[1];     // [B]
    const float* W    = (const float*)d_in[2];   // [S, D, O]
    const float* bias = (const float*)d_in[3];   // [S, O]
    float*       out  = (float*)d_out;           // [B, O]

    (void)in_sizes; (void)n_in; (void)out_size;

    k_pre<<<NBLK + TBLK, 256>>>(sid, (const float4*)W);
    k_scan<<<1, 64>>>();
    k_scatter<<<NBLK, 256>>>(sid);
    k_gemm<<<B_N / (SPW * 8), 256>>>(x, sid, bias, out);
}